// round 6
// baseline (speedup 1.0000x reference)
#include <cuda_runtime.h>
#include <math.h>

#define B_ROWS 32768
#define C_CLS  1000
#define NBLK   (B_ROWS / 8)

__device__ float        g_blk_loss[NBLK];
__device__ unsigned int g_ctr;           // wraps to 0 each launch via atomicInc

typedef unsigned long long u64;

__device__ __forceinline__ float frcp(float x) {
    float r; asm("rcp.approx.f32 %0, %1;" : "=f"(r) : "f"(x)); return r;
}
__device__ __forceinline__ float fpow_fast(float x, float p) {
    float lg; asm("lg2.approx.f32 %0, %1;" : "=f"(lg) : "f"(x));
    float e = lg * p;
    float r; asm("ex2.approx.f32 %0, %1;" : "=f"(r) : "f"(e)); return r;
}
__device__ __forceinline__ u64 pk(float x, float y) {
    u64 r; asm("mov.b64 %0, {%1,%2};" : "=l"(r) : "f"(x), "f"(y)); return r;
}
__device__ __forceinline__ void upk(u64 v, float& x, float& y) {
    asm("mov.b64 {%0,%1}, %2;" : "=f"(x), "=f"(y) : "l"(v));
}
__device__ __forceinline__ u64 fma2(u64 a, u64 b, u64 c) {
    u64 d; asm("fma.rn.f32x2 %0, %1, %2, %3;" : "=l"(d) : "l"(a), "l"(b), "l"(c)); return d;
}
__device__ __forceinline__ u64 mul2(u64 a, u64 b) {
    u64 d; asm("mul.rn.f32x2 %0, %1, %2;" : "=l"(d) : "l"(a), "l"(b)); return d;
}
__device__ __forceinline__ u64 rcp2(u64 v) {      // 2x MUFU
    float x, y; upk(v, x, y);
    return pk(frcp(x), frcp(y));
}
__device__ __forceinline__ float wredux(float v) {
    #pragma unroll
    for (int o = 16; o; o >>= 1) v += __shfl_xor_sync(0xffffffffu, v, o);
    return v;
}

// packed rcp seed; no cross-field borrow: low field >= bits(nr) for nr in [-inf,-1]
#define MAGIC2 0xFEF311C3FEF311C3ULL

// One Z pass: Z = sum (1+u*s)^-5 over the warp's 1000 elements.
// MODE 0: sloppy (1 Newton) s-update pass. MODE 1: precise (2 Newton) update.
// MODE 2: precise final pass; overwrites u2[i] with inv = 1/(1+u*s).
// Pairs 0..13 are mask-free (elements q<224+26): FMA-pipe Newton.
// Pairs 14,15 (j=7) may hold +inf (masked): MUFU rcp (inf -> 0).
template<int MODE>
__device__ __forceinline__ float zpass(u64* u2, float s)
{
    const u64 ONE2  = pk(1.0f, 1.0f);
    const u64 nONE2 = pk(-1.0f, -1.0f);
    const u64 TWO2  = pk(2.0f, 2.0f);
    const u64 s2    = pk(s, s);
    const u64 ns2   = pk(-s, -s);
    u64 z2 = pk(0.0f, 0.0f);
    #pragma unroll
    for (int i = 0; i < 14; ++i) {
        u64 nr2 = fma2(u2[i], ns2, nONE2);     // -(1+u*s) in [-2.6,-1]
        u64 y   = MAGIC2 - nr2;                // ~5% seed for 1/r (ALU pipe)
        y = mul2(y, fma2(nr2, y, TWO2));       // Newton 1 (~3e-3)
        if (MODE != 0) y = mul2(y, fma2(nr2, y, TWO2)); // Newton 2 (~1e-5)
        if (MODE == 2) u2[i] = y;              // keep inv for fused loss
        u64 q2 = mul2(y, y);
        u64 q4 = mul2(q2, q2);
        z2 = fma2(q4, y, z2);                  // += r^-5
    }
    #pragma unroll
    for (int i = 14; i < 16; ++i) {
        u64 r2   = fma2(u2[i], s2, ONE2);      // inf for masked
        u64 inv2 = rcp2(r2);                   // 0 for masked
        if (MODE == 2) u2[i] = inv2;
        u64 q2 = mul2(inv2, inv2);
        u64 q4 = mul2(q2, q2);
        z2 = fma2(q4, inv2, z2);
    }
    float zx, zy; upk(z2, zx, zy);
    return wredux(zx + zy);
}

// ---------------------------------------------------------------------------
// One warp per row; 32 elems/lane as 16 packed f32x2 regs.
// 3 s-updates (2 sloppy + 1 precise) + precise final pass (stores inv).
// zp = Zf^0.2, sf = 1/zp, c = sf/s3 - 1 (~6e-4).
// Fused loss: inv_f = sf*inv*((1-c) + c*inv)  -- exact to O(c^2).
// L = A_off - B_off*inv_f + (1/1.2)*inv_f^6 ; truth fix scalar on lane 0.
// Last block (atomicInc) reduces all 4096 block partials + weight sum.
// ---------------------------------------------------------------------------
__global__ __launch_bounds__(256)
void bitempered_row_kernel(const float* __restrict__ logits,
                           const int*   __restrict__ truth,
                           const float* __restrict__ weight,
                           float* __restrict__ out,
                           float A_off, float B_off, float dA, float dB)
{
    __shared__ float sm[16];
    __shared__ int   smlast;
    const int lane = threadIdx.x & 31;
    const int wib  = threadIdx.x >> 5;
    const int row  = blockIdx.x * 8 + wib;

    const int   t  = truth[row];                       // uniform per warp
    const float xt = logits[(size_t)row * C_CLS + t];  // truth-class logit
    const float wt = __ldg(weight + t);

    const float4* xrow = (const float4*)(logits + (size_t)row * C_CLS);

    u64 u2[16];
    float xmax = -INFINITY;
    #pragma unroll
    for (int j = 0; j < 8; ++j) {
        const int q = lane + 32 * j;            // float4 index, valid iff q < 250
        float4 v;
        if (q < 250) v = xrow[q];
        else         v = make_float4(-INFINITY, -INFINITY, -INFINITY, -INFINITY);
        u2[2*j]   = pk(v.x, v.y);
        u2[2*j+1] = pk(v.z, v.w);
        xmax = fmaxf(xmax, fmaxf(fmaxf(v.x, v.y), fmaxf(v.z, v.w)));
    }
    #pragma unroll
    for (int o = 16; o; o >>= 1)
        xmax = fmaxf(xmax, __shfl_xor_sync(0xffffffffu, xmax, o));

    {
        const u64 cm = pk(-0.2f, -0.2f);
        const u64 ca = pk(0.2f * xmax, 0.2f * xmax);
        #pragma unroll
        for (int i = 0; i < 16; ++i)
            u2[i] = fma2(u2[i], cm, ca);        // masked raw -inf -> +inf
    }

    // 3 s-updates, then final pass (stores inv at s3)
    float s1 = fpow_fast(zpass<0>(u2, 1.0f), -0.2f);
    float s2 = fpow_fast(zpass<0>(u2, s1),  -0.2f);
    float s3 = fpow_fast(zpass<1>(u2, s2),  -0.2f);
    float zf = zpass<2>(u2, s3);

    const float zp = fpow_fast(zf, 0.2f);      // 1 - 0.2*(x - nc) = u + zp
    const float sf = frcp(zp);
    const float c  = fmaf(sf, frcp(s3), -1.0f); // sf/s3 - 1, ~6e-4
    const u64   k0 = pk(sf * (1.0f - c), sf * (1.0f - c));
    const u64   k1 = pk(sf * c, sf * c);
    const u64   A2  = pk(A_off, A_off);
    const u64   nB2 = pk(-B_off, -B_off);
    const u64   C2  = pk(1.0f / 1.2f, 1.0f / 1.2f);

    const float4* w4 = (const float4*)weight;
    u64 acc2 = pk(0.0f, 0.0f);
    #pragma unroll
    for (int j = 0; j < 8; ++j) {
        const int q = lane + 32 * j;
        if (q < 250) {
            float4 wv = w4[q];
            u64 w2[2] = { pk(wv.x, wv.y), pk(wv.z, wv.w) };
            #pragma unroll
            for (int h = 0; h < 2; ++h) {
                u64 inv = u2[2*j + h];
                u64 tcr = fma2(inv, k1, k0);       // sf*((1-c)+c*inv)
                u64 m   = mul2(inv, tcr);          // inv_f = p^{0.2}
                u64 q2  = mul2(m, m);
                u64 q4  = mul2(q2, q2);
                u64 p12 = mul2(q4, q2);            // p^{1.2}
                u64 t2  = fma2(m, nB2, A2);        // A_off - B_off*inv_f
                u64 L2  = fma2(p12, C2, t2);
                acc2 = fma2(w2[h], L2, acc2);
            }
        }
    }
    float ax, ay; upk(acc2, ax, ay);
    float acc = wredux(ax + ay);

    if (lane == 0) {
        const float ut   = fmaf(xt, -0.2f, 0.2f * xmax);
        const float invt = frcp(ut + zp);
        acc += wt * fmaf(-dB, invt, dA);
        sm[wib] = acc;
    }
    __syncthreads();
    if (threadIdx.x == 0) {
        float bs = 0.0f;
        #pragma unroll
        for (int i = 0; i < 8; ++i) bs += sm[i];
        g_blk_loss[blockIdx.x] = bs;
        __threadfence();
        unsigned old = atomicInc(&g_ctr, NBLK - 1);   // wraps to 0 -> resets per launch
        smlast = (old == NBLK - 1);
    }
    __syncthreads();

    // last block reduces everything
    if (smlast) {
        const int tid = threadIdx.x;
        float ls = 0.0f;
        #pragma unroll
        for (int i = 0; i < NBLK / 256; ++i)
            ls += __ldcg(&g_blk_loss[tid + i * 256]);
        float ws = 0.0f;
        if (tid < 250) {
            float4 wv = w4[tid];
            ws = (wv.x + wv.y) + (wv.z + wv.w);
        }
        ls = wredux(ls);
        ws = wredux(ws);
        if (lane == 0) { sm[wib] = ls; sm[8 + wib] = ws; }
        __syncthreads();
        if (tid == 0) {
            float lsum = 0.0f, wsum = 0.0f;
            #pragma unroll
            for (int i = 0; i < 8; ++i) { lsum += sm[i]; wsum += sm[8 + i]; }
            out[0] = lsum * ((float)C_CLS / wsum) * (1.0f / (float)B_ROWS);
        }
    }
}

// ---------------------------------------------------------------------------
extern "C" void kernel_launch(void* const* d_in, const int* in_sizes, int n_in,
                              void* d_out, int out_size)
{
    const float* logits = (const float*)d_in[0];
    const int*   truth  = (const int*)  d_in[1];
    const float* weight = (const float*)d_in[2];
    float* out = (float*)d_out;

    const double T1 = 0.8, SM = 0.05;
    const double Cd = (double)C_CLS;
    const double y_on  = (1.0 - SM * Cd / (Cd - 1.0)) + SM / (Cd - 1.0);
    const double y_off = SM / (Cd - 1.0);
    auto logt1 = [](double v) { return (pow(v, 0.2) - 1.0) / 0.2; };
    auto Cy = [&](double y) {
        return y * logt1(y + 1e-10) - pow(y, 2.0 - T1) / (2.0 - T1);
    };
    const float A_on  = (float)(Cy(y_on)  + 5.0 * y_on);
    const float A_off = (float)(Cy(y_off) + 5.0 * y_off);
    const float B_on  = (float)(5.0 * y_on);
    const float B_off = (float)(5.0 * y_off);

    bitempered_row_kernel<<<NBLK, 256>>>(logits, truth, weight, out,
                                         A_off, B_off, A_on - A_off, B_on - B_off);
}

// round 7
// speedup vs baseline: 1.5339x; 1.5339x over previous
#include <cuda_runtime.h>
#include <math.h>

#define B_ROWS 32768
#define C_CLS  1000
#define NBLK   (B_ROWS / 8)

__device__ float g_blk_loss[NBLK];

typedef unsigned long long u64;

__device__ __forceinline__ float frcp(float x) {
    float r; asm("rcp.approx.f32 %0, %1;" : "=f"(r) : "f"(x)); return r;
}
__device__ __forceinline__ float fpow_fast(float x, float p) {
    float lg; asm("lg2.approx.f32 %0, %1;" : "=f"(lg) : "f"(x));
    float e = lg * p;
    float r; asm("ex2.approx.f32 %0, %1;" : "=f"(r) : "f"(e)); return r;
}
__device__ __forceinline__ u64 pk(float x, float y) {
    u64 r; asm("mov.b64 %0, {%1,%2};" : "=l"(r) : "f"(x), "f"(y)); return r;
}
__device__ __forceinline__ void upk(u64 v, float& x, float& y) {
    asm("mov.b64 {%0,%1}, %2;" : "=f"(x), "=f"(y) : "l"(v));
}
__device__ __forceinline__ u64 fma2(u64 a, u64 b, u64 c) {
    u64 d; asm("fma.rn.f32x2 %0, %1, %2, %3;" : "=l"(d) : "l"(a), "l"(b), "l"(c)); return d;
}
__device__ __forceinline__ u64 mul2(u64 a, u64 b) {
    u64 d; asm("mul.rn.f32x2 %0, %1, %2;" : "=l"(d) : "l"(a), "l"(b)); return d;
}
__device__ __forceinline__ u64 rcp2(u64 v) {      // 2x MUFU
    float x, y; upk(v, x, y);
    return pk(frcp(x), frcp(y));
}
__device__ __forceinline__ float wredux(float v) {
    #pragma unroll
    for (int o = 16; o; o >>= 1) v += __shfl_xor_sync(0xffffffffu, v, o);
    return v;
}

// packed rcp seed; no cross-field borrow: low field >= bits(nr) for nr in [-inf,-1]
#define MAGIC2 0xFEF311C3FEF311C3ULL

// Update pass: Z = sum (1+u*s)^-5.  FMA pipe is the binder, so only
// pairs 0..5 use FMA-pipe Newton; pairs 6..15 use MUFU rcp (has headroom;
// also inf-safe for the masked elements in pairs 14,15).
__device__ __forceinline__ float zpass_update(const u64* u2, float s)
{
    const u64 ONE2  = pk(1.0f, 1.0f);
    const u64 nONE2 = pk(-1.0f, -1.0f);
    const u64 TWO2  = pk(2.0f, 2.0f);
    const u64 s2    = pk(s, s);
    const u64 ns2   = pk(-s, -s);
    u64 z2 = pk(0.0f, 0.0f);
    #pragma unroll
    for (int i = 0; i < 6; ++i) {
        u64 nr2 = fma2(u2[i], ns2, nONE2);     // -(1+u*s) in [-2.6,-1]
        u64 y   = MAGIC2 - nr2;                // ~5% seed (ALU pipe)
        y = mul2(y, fma2(nr2, y, TWO2));       // Newton 1 (~3e-3)
        y = mul2(y, fma2(nr2, y, TWO2));       // Newton 2 (~1e-5)
        u64 q2 = mul2(y, y);
        u64 q4 = mul2(q2, q2);
        z2 = fma2(q4, y, z2);                  // += r^-5
    }
    #pragma unroll
    for (int i = 6; i < 16; ++i) {
        u64 r2   = fma2(u2[i], s2, ONE2);      // inf for masked
        u64 inv2 = rcp2(r2);                   // 0 for masked
        u64 q2 = mul2(inv2, inv2);
        u64 q4 = mul2(q2, q2);
        z2 = fma2(q4, inv2, z2);
    }
    float zx, zy; upk(z2, zx, zy);
    return wredux(zx + zy);
}

// ---------------------------------------------------------------------------
// One warp per row; 32 elems/lane as 16 packed f32x2 regs.
// 3 s-updates, then a FINAL pass fused with the loss: alongside Zf it
// accumulates weighted power sums  S1=Σw·inv, S2=Σw·inv², S6=Σw·inv⁶,
// S7=Σw·inv⁷  (inv = 1/(1+u·s3)).  With zp=Zf^0.2, sf=1/zp, c=sf/s3-1:
//   Σw·inv_f  = sf  ·((1-c)·S1 + c·S2)        (exact to O(c²))
//   Σw·inv_f⁶ = sf⁶·((1-6c)·S6 + 6c·S7)
//   row_partial = -B_off·Σw·inv_f + (1/1.2)·Σw·inv_f⁶ + wt·(dA - dB·invt)
// The A_off·Σw term is a global constant, folded into the reduce kernel.
// ---------------------------------------------------------------------------
__global__ __launch_bounds__(256)
void bitempered_row_kernel(const float* __restrict__ logits,
                           const int*   __restrict__ truth,
                           const float* __restrict__ weight,
                           float B_off, float dA, float dB)
{
    __shared__ float sm[8];
    const int lane = threadIdx.x & 31;
    const int wib  = threadIdx.x >> 5;
    const int row  = blockIdx.x * 8 + wib;

    const int   t  = truth[row];                       // uniform per warp
    const float xt = logits[(size_t)row * C_CLS + t];  // truth-class logit
    const float wt = __ldg(weight + t);

    const float4* xrow = (const float4*)(logits + (size_t)row * C_CLS);

    u64 u2[16];
    float xmax = -INFINITY;
    #pragma unroll
    for (int j = 0; j < 8; ++j) {
        const int q = lane + 32 * j;            // float4 index, valid iff q < 250
        float4 v;
        if (q < 250) v = xrow[q];
        else         v = make_float4(-INFINITY, -INFINITY, -INFINITY, -INFINITY);
        u2[2*j]   = pk(v.x, v.y);
        u2[2*j+1] = pk(v.z, v.w);
        xmax = fmaxf(xmax, fmaxf(fmaxf(v.x, v.y), fmaxf(v.z, v.w)));
    }
    #pragma unroll
    for (int o = 16; o; o >>= 1)
        xmax = fmaxf(xmax, __shfl_xor_sync(0xffffffffu, xmax, o));

    {
        const u64 cm = pk(-0.2f, -0.2f);
        const u64 ca = pk(0.2f * xmax, 0.2f * xmax);
        #pragma unroll
        for (int i = 0; i < 16; ++i)
            u2[i] = fma2(u2[i], cm, ca);        // masked raw -inf -> +inf
    }

    // 3 s-updates
    float s1 = fpow_fast(zpass_update(u2, 1.0f), -0.2f);
    float sA = fpow_fast(zpass_update(u2, s1),  -0.2f);
    float s3 = fpow_fast(zpass_update(u2, sA),  -0.2f);

    // Final pass fused with loss accumulation
    const u64 ONE2  = pk(1.0f, 1.0f);
    const u64 nONE2 = pk(-1.0f, -1.0f);
    const u64 TWO2  = pk(2.0f, 2.0f);
    const u64 s32   = pk(s3, s3);
    const u64 ns32  = pk(-s3, -s3);
    const float4* w4 = (const float4*)weight;

    u64 z2 = pk(0.0f, 0.0f), S1 = z2, S2 = z2, S6 = z2, S7 = z2;
    #pragma unroll
    for (int j = 0; j < 8; ++j) {
        const int q = lane + 32 * j;
        float4 wv;
        if (q < 250) wv = w4[q];
        else         wv = make_float4(0.0f, 0.0f, 0.0f, 0.0f);
        u64 w2[2] = { pk(wv.x, wv.y), pk(wv.z, wv.w) };
        #pragma unroll
        for (int h = 0; h < 2; ++h) {
            u64 y;
            u64 q2, q4;
            if (j < 5) {  // mask-free classes: FMA-pipe Newton
                u64 nr2 = fma2(u2[2*j+h], ns32, nONE2);
                y = MAGIC2 - nr2;
                y = mul2(y, fma2(nr2, y, TWO2));
                y = mul2(y, fma2(nr2, y, TWO2));
            } else {      // MUFU (inf-safe for masked: inv -> 0)
                u64 r2 = fma2(u2[2*j+h], s32, ONE2);
                y = rcp2(r2);
            }
            q2 = mul2(y, y);
            q4 = mul2(q2, q2);
            z2 = fma2(q4, y, z2);              // Zf += inv^5
            S1 = fma2(y,  w2[h], S1);          // += w*inv
            S2 = fma2(q2, w2[h], S2);          // += w*inv^2
            u64 p6 = mul2(q4, q2);
            S6 = fma2(p6, w2[h], S6);          // += w*inv^6
            u64 p7 = mul2(p6, y);
            S7 = fma2(p7, w2[h], S7);          // += w*inv^7
        }
    }
    float a, b;
    upk(z2, a, b); const float zf  = wredux(a + b);
    upk(S1, a, b); const float rS1 = wredux(a + b);
    upk(S2, a, b); const float rS2 = wredux(a + b);
    upk(S6, a, b); const float rS6 = wredux(a + b);
    upk(S7, a, b); const float rS7 = wredux(a + b);

    if (lane == 0) {
        const float zp = fpow_fast(zf, 0.2f);         // u + zp = 1 - 0.2*(x-nc)
        const float sf = frcp(zp);
        const float c  = fmaf(sf, frcp(s3), -1.0f);   // sf/s3 - 1 (~6e-4)
        const float sf2 = sf * sf;
        const float sf6 = sf2 * sf2 * sf2;
        const float sumInv  = sf  * fmaf(c, rS2 - rS1, rS1);         // (1-c)S1 + c S2
        const float sumInv6 = sf6 * fmaf(6.0f * c, rS7 - rS6, rS6);  // (1-6c)S6 + 6c S7
        const float ut   = fmaf(xt, -0.2f, 0.2f * xmax);
        const float invt = frcp(ut + zp);
        float acc = fmaf(-B_off, sumInv, sumInv6 * (1.0f / 1.2f));
        acc += wt * fmaf(-dB, invt, dA);
        sm[wib] = acc;
    }
    __syncthreads();
    if (threadIdx.x == 0) {
        float bs = 0.0f;
        #pragma unroll
        for (int i = 0; i < 8; ++i) bs += sm[i];
        g_blk_loss[blockIdx.x] = bs;
    }
}

// ---------------------------------------------------------------------------
// Kernel 2: reduce block partials + weight sum; fold in the A_off*Sw term:
//   out = lsum * C/(wsum*B) + A_off*C
// ---------------------------------------------------------------------------
__global__ __launch_bounds__(1024)
void bitempered_reduce_kernel(const float* __restrict__ weight,
                              float* __restrict__ out, float A_off)
{
    __shared__ float sm[32];
    const int tid  = threadIdx.x;
    const int lane = tid & 31;
    const int w    = tid >> 5;

    float ws = (tid < C_CLS) ? weight[tid] : 0.0f;
    ws = wredux(ws);
    if (lane == 0) sm[w] = ws;
    __syncthreads();
    float wsum = 0.0f;
    if (tid == 0) {
        #pragma unroll
        for (int i = 0; i < 32; ++i) wsum += sm[i];
    }
    __syncthreads();

    float ls = 0.0f;
    #pragma unroll
    for (int i = 0; i < NBLK / 1024; ++i) ls += g_blk_loss[tid + i * 1024];
    ls = wredux(ls);
    if (lane == 0) sm[w] = ls;
    __syncthreads();
    if (tid == 0) {
        float lsum = 0.0f;
        #pragma unroll
        for (int i = 0; i < 32; ++i) lsum += sm[i];
        out[0] = lsum * ((float)C_CLS / wsum) * (1.0f / (float)B_ROWS)
               + A_off * (float)C_CLS;
    }
}

// ---------------------------------------------------------------------------
extern "C" void kernel_launch(void* const* d_in, const int* in_sizes, int n_in,
                              void* d_out, int out_size)
{
    const float* logits = (const float*)d_in[0];
    const int*   truth  = (const int*)  d_in[1];
    const float* weight = (const float*)d_in[2];
    float* out = (float*)d_out;

    const double T1 = 0.8, SM = 0.05;
    const double Cd = (double)C_CLS;
    const double y_on  = (1.0 - SM * Cd / (Cd - 1.0)) + SM / (Cd - 1.0);
    const double y_off = SM / (Cd - 1.0);
    auto logt1 = [](double v) { return (pow(v, 0.2) - 1.0) / 0.2; };
    auto Cy = [&](double y) {
        return y * logt1(y + 1e-10) - pow(y, 2.0 - T1) / (2.0 - T1);
    };
    const float A_on  = (float)(Cy(y_on)  + 5.0 * y_on);
    const float A_off = (float)(Cy(y_off) + 5.0 * y_off);
    const float B_on  = (float)(5.0 * y_on);
    const float B_off = (float)(5.0 * y_off);

    bitempered_row_kernel<<<NBLK, 256>>>(logits, truth, weight,
                                         B_off, A_on - A_off, B_on - B_off);
    bitempered_reduce_kernel<<<1, 1024>>>(weight, out, A_off);
}

// round 8
// speedup vs baseline: 1.8393x; 1.1991x over previous
#include <cuda_runtime.h>
#include <math.h>

#define B_ROWS 32768
#define C_CLS  1000
#define NBLK   (B_ROWS / 8)

__device__ float g_blk_loss[NBLK];

typedef unsigned long long u64;

__device__ __forceinline__ float frcp(float x) {
    float r; asm("rcp.approx.f32 %0, %1;" : "=f"(r) : "f"(x)); return r;
}
__device__ __forceinline__ float fpow_fast(float x, float p) {
    float lg; asm("lg2.approx.f32 %0, %1;" : "=f"(lg) : "f"(x));
    float e = lg * p;
    float r; asm("ex2.approx.f32 %0, %1;" : "=f"(r) : "f"(e)); return r;
}
__device__ __forceinline__ u64 pk(float x, float y) {
    u64 r; asm("mov.b64 %0, {%1,%2};" : "=l"(r) : "f"(x), "f"(y)); return r;
}
__device__ __forceinline__ void upk(u64 v, float& x, float& y) {
    asm("mov.b64 {%0,%1}, %2;" : "=f"(x), "=f"(y) : "l"(v));
}
__device__ __forceinline__ u64 fma2(u64 a, u64 b, u64 c) {
    u64 d; asm("fma.rn.f32x2 %0, %1, %2, %3;" : "=l"(d) : "l"(a), "l"(b), "l"(c)); return d;
}
__device__ __forceinline__ u64 mul2(u64 a, u64 b) {
    u64 d; asm("mul.rn.f32x2 %0, %1, %2;" : "=l"(d) : "l"(a), "l"(b)); return d;
}
__device__ __forceinline__ u64 rcp2(u64 v) {      // 2x MUFU
    float x, y; upk(v, x, y);
    return pk(frcp(x), frcp(y));
}
__device__ __forceinline__ float wredux(float v) {
    #pragma unroll
    for (int o = 16; o; o >>= 1) v += __shfl_xor_sync(0xffffffffu, v, o);
    return v;
}

// packed rcp seed; no cross-field borrow: low field >= bits(nr) for nr in [-3,-1]
#define MAGIC2 0xFEF311C3FEF311C3ULL

// Update pass: Z = sum (1+u*s)^-5.  Pairs 0..13 (mask-free) use FMA-pipe
// Newton (NSTEP iterations); pairs 14,15 may hold +inf -> MUFU rcp (inf->0).
template<int NSTEP>
__device__ __forceinline__ float zpass_update(const u64* u2, float s)
{
    const u64 ONE2  = pk(1.0f, 1.0f);
    const u64 nONE2 = pk(-1.0f, -1.0f);
    const u64 TWO2  = pk(2.0f, 2.0f);
    const u64 sv    = pk(s, s);
    const u64 nsv   = pk(-s, -s);
    u64 z2 = pk(0.0f, 0.0f);
    #pragma unroll
    for (int i = 0; i < 14; ++i) {
        u64 nr2 = fma2(u2[i], nsv, nONE2);     // -(1+u*s) in [-3,-1]
        u64 y   = MAGIC2 - nr2;                // ~5% seed (ALU pipe)
        y = mul2(y, fma2(nr2, y, TWO2));       // Newton 1 (~3e-3)
        if (NSTEP == 2)
            y = mul2(y, fma2(nr2, y, TWO2));   // Newton 2 (~1e-5)
        u64 q2 = mul2(y, y);
        u64 q4 = mul2(q2, q2);
        z2 = fma2(q4, y, z2);                  // += r^-5
    }
    #pragma unroll
    for (int i = 14; i < 16; ++i) {
        u64 r2   = fma2(u2[i], sv, ONE2);      // inf for masked
        u64 inv2 = rcp2(r2);                   // 0 for masked
        u64 q2 = mul2(inv2, inv2);
        u64 q4 = mul2(q2, q2);
        z2 = fma2(q4, inv2, z2);
    }
    float zx, zy; upk(z2, zx, zy);
    return wredux(zx + zy);
}

// ---------------------------------------------------------------------------
// One warp per row; 32 elems/lane as 16 packed f32x2 regs.
// s1 = g_sloppy(1); s2 = g(s1); pass 3 computes s3 = g(s2) AND the weighted
// power sums S1,S2,S6,S7,S8 at inv = 1/(1+u*s2).  Aitken: s* ~= sext from
// (s1,s2,s3) (valid: s2,s3 use the same precise map).  With sf = sext,
// zp = 1/sf, c = sf/s2 - 1 (~1e-3):
//   Σw/(u+zp)    = sf ·(S1 - c(S1-S2))                        + O(c²)·B_off
//   Σw/(u+zp)^6  = sf⁶·(S6 - 6c(S6-S7) + 21c²(S6-2S7+S8))     + O(c³)
//   row = -B_off·ΣwInv + (1/1.2)·ΣwInv6 + wt·(dA - dB·invt)
// The A_off·Σw constant is folded into the reduce kernel.
// ---------------------------------------------------------------------------
__global__ __launch_bounds__(256)
void bitempered_row_kernel(const float* __restrict__ logits,
                           const int*   __restrict__ truth,
                           const float* __restrict__ weight,
                           float B_off, float dA, float dB)
{
    __shared__ float sm[8];
    const int lane = threadIdx.x & 31;
    const int wib  = threadIdx.x >> 5;
    const int row  = blockIdx.x * 8 + wib;

    const int   t  = truth[row];                       // uniform per warp
    const float xt = logits[(size_t)row * C_CLS + t];  // truth-class logit
    const float wt = __ldg(weight + t);

    const float4* xrow = (const float4*)(logits + (size_t)row * C_CLS);

    u64 u2[16];
    float xmax = -INFINITY;
    #pragma unroll
    for (int j = 0; j < 8; ++j) {
        const int q = lane + 32 * j;            // float4 index, valid iff q < 250
        float4 v;
        if (q < 250) v = xrow[q];
        else         v = make_float4(-INFINITY, -INFINITY, -INFINITY, -INFINITY);
        u2[2*j]   = pk(v.x, v.y);
        u2[2*j+1] = pk(v.z, v.w);
        xmax = fmaxf(xmax, fmaxf(fmaxf(v.x, v.y), fmaxf(v.z, v.w)));
    }
    #pragma unroll
    for (int o = 16; o; o >>= 1)
        xmax = fmaxf(xmax, __shfl_xor_sync(0xffffffffu, xmax, o));

    {
        const u64 cm = pk(-0.2f, -0.2f);
        const u64 ca = pk(0.2f * xmax, 0.2f * xmax);
        #pragma unroll
        for (int i = 0; i < 16; ++i)
            u2[i] = fma2(u2[i], cm, ca);        // masked raw -inf -> +inf
    }

    // s1 (sloppy map), s2 (precise map)
    const float s1 = fpow_fast(zpass_update<1>(u2, 1.0f), -0.2f);
    const float s2 = fpow_fast(zpass_update<2>(u2, s1),  -0.2f);

    // Pass 3: precise map at s2 + weighted power sums
    const u64 ONE2  = pk(1.0f, 1.0f);
    const u64 nONE2 = pk(-1.0f, -1.0f);
    const u64 TWO2  = pk(2.0f, 2.0f);
    const u64 sv    = pk(s2, s2);
    const u64 nsv   = pk(-s2, -s2);
    const float4* w4 = (const float4*)weight;

    u64 z2 = pk(0.0f, 0.0f);
    u64 S1a = z2, S2a = z2, S6a = z2, S7a = z2, S8a = z2;
    #pragma unroll
    for (int j = 0; j < 8; ++j) {
        const int q = lane + 32 * j;
        float4 wv;
        if (q < 250) wv = w4[q];
        else         wv = make_float4(0.0f, 0.0f, 0.0f, 0.0f);
        u64 w2[2] = { pk(wv.x, wv.y), pk(wv.z, wv.w) };
        #pragma unroll
        for (int h = 0; h < 2; ++h) {
            const int i = 2*j + h;
            u64 y;
            if (i < 14) {                       // mask-free: FMA-pipe Newton
                u64 nr2 = fma2(u2[i], nsv, nONE2);
                y = MAGIC2 - nr2;
                y = mul2(y, fma2(nr2, y, TWO2));
                y = mul2(y, fma2(nr2, y, TWO2));
            } else {                            // MUFU (inf-safe: inv -> 0)
                u64 r2 = fma2(u2[i], sv, ONE2);
                y = rcp2(r2);
            }
            u64 q2 = mul2(y, y);
            u64 q4 = mul2(q2, q2);
            z2  = fma2(q4, y, z2);              // Z  += inv^5
            S1a = fma2(y,  w2[h], S1a);         // += w*inv
            S2a = fma2(q2, w2[h], S2a);         // += w*inv^2
            u64 p6 = mul2(q4, q2);
            S6a = fma2(p6, w2[h], S6a);         // += w*inv^6
            u64 p7 = mul2(p6, y);
            S7a = fma2(p7, w2[h], S7a);         // += w*inv^7
            u64 p8 = mul2(p7, y);
            S8a = fma2(p8, w2[h], S8a);         // += w*inv^8
        }
    }
    float a, b;
    upk(z2,  a, b); const float z3  = wredux(a + b);
    upk(S1a, a, b); const float S1 = wredux(a + b);
    upk(S2a, a, b); const float S2 = wredux(a + b);
    upk(S6a, a, b); const float S6 = wredux(a + b);
    upk(S7a, a, b); const float S7 = wredux(a + b);
    upk(S8a, a, b); const float S8 = wredux(a + b);

    if (lane == 0) {
        const float s3 = fpow_fast(z3, -0.2f);
        // Aitken extrapolation to the fixed point
        const float d1  = s2 - s1;
        const float d2  = s3 - s2;
        const float den = d2 - d1;
        float sf = s3;
        if (fabsf(den) > 1e-12f) sf = s3 - d2 * d2 * frcp(den);
        const float zp = frcp(sf);                    // u + zp = 1 - 0.2*(x-nc)
        const float c  = fmaf(sf, frcp(s2), -1.0f);   // sums were taken at s2
        const float sf2 = sf * sf;
        const float sf6 = sf2 * sf2 * sf2;
        const float sumInv  = sf * fmaf(c, S2 - S1, S1);
        const float t6 = S6 - 6.0f * c * (S6 - S7)
                       + 21.0f * c * c * (S6 - 2.0f * S7 + S8);
        const float sumInv6 = sf6 * t6;
        const float ut   = fmaf(xt, -0.2f, 0.2f * xmax);
        const float invt = frcp(ut + zp);
        float acc = fmaf(-B_off, sumInv, sumInv6 * (1.0f / 1.2f));
        acc += wt * fmaf(-dB, invt, dA);
        sm[wib] = acc;
    }
    __syncthreads();
    if (threadIdx.x == 0) {
        float bs = 0.0f;
        #pragma unroll
        for (int i = 0; i < 8; ++i) bs += sm[i];
        g_blk_loss[blockIdx.x] = bs;
    }
}

// ---------------------------------------------------------------------------
// Kernel 2: reduce block partials + weight sum; fold in the A_off*Sw term:
//   out = lsum * C/(wsum*B) + A_off*C
// ---------------------------------------------------------------------------
__global__ __launch_bounds__(1024)
void bitempered_reduce_kernel(const float* __restrict__ weight,
                              float* __restrict__ out, float A_off)
{
    __shared__ float sm[32];
    const int tid  = threadIdx.x;
    const int lane = tid & 31;
    const int w    = tid >> 5;

    float ws = (tid < C_CLS) ? weight[tid] : 0.0f;
    ws = wredux(ws);
    if (lane == 0) sm[w] = ws;
    __syncthreads();
    float wsum = 0.0f;
    if (tid == 0) {
        #pragma unroll
        for (int i = 0; i < 32; ++i) wsum += sm[i];
    }
    __syncthreads();

    const float4* p4 = (const float4*)g_blk_loss;   // NBLK/4 = 1024 float4
    float4 lv = p4[tid];
    float ls = (lv.x + lv.y) + (lv.z + lv.w);
    ls = wredux(ls);
    if (lane == 0) sm[w] = ls;
    __syncthreads();
    if (tid == 0) {
        float lsum = 0.0f;
        #pragma unroll
        for (int i = 0; i < 32; ++i) lsum += sm[i];
        out[0] = lsum * ((float)C_CLS / wsum) * (1.0f / (float)B_ROWS)
               + A_off * (float)C_CLS;
    }
}

// ---------------------------------------------------------------------------
extern "C" void kernel_launch(void* const* d_in, const int* in_sizes, int n_in,
                              void* d_out, int out_size)
{
    const float* logits = (const float*)d_in[0];
    const int*   truth  = (const int*)  d_in[1];
    const float* weight = (const float*)d_in[2];
    float* out = (float*)d_out;

    const double T1 = 0.8, SM = 0.05;
    const double Cd = (double)C_CLS;
    const double y_on  = (1.0 - SM * Cd / (Cd - 1.0)) + SM / (Cd - 1.0);
    const double y_off = SM / (Cd - 1.0);
    auto logt1 = [](double v) { return (pow(v, 0.2) - 1.0) / 0.2; };
    auto Cy = [&](double y) {
        return y * logt1(y + 1e-10) - pow(y, 2.0 - T1) / (2.0 - T1);
    };
    const float A_on  = (float)(Cy(y_on)  + 5.0 * y_on);
    const float A_off = (float)(Cy(y_off) + 5.0 * y_off);
    const float B_on  = (float)(5.0 * y_on);
    const float B_off = (float)(5.0 * y_off);

    bitempered_row_kernel<<<NBLK, 256>>>(logits, truth, weight,
                                         B_off, A_on - A_off, B_on - B_off);
    bitempered_reduce_kernel<<<1, 1024>>>(weight, out, A_off);
}

// round 9
// speedup vs baseline: 2.1813x; 1.1860x over previous
#include <cuda_runtime.h>
#include <math.h>

#define B_ROWS 32768
#define C_CLS  1000
#define NBLK   (B_ROWS / 8)

// packed accumulator: bits[63:52] arrival count, bits[51:0] biased fixed-point sum
__device__ unsigned long long g_acc;   // zero-init; self-resets each launch

typedef unsigned long long u64;

#define SCALE_F   268435456.0f           /* 2^28 */
#define INV_SCALE (1.0f / 268435456.0f)
#define BIAS_LL   (1ll << 39)

__device__ __forceinline__ float frcp(float x) {
    float r; asm("rcp.approx.f32 %0, %1;" : "=f"(r) : "f"(x)); return r;
}
__device__ __forceinline__ float fpow_fast(float x, float p) {
    float lg; asm("lg2.approx.f32 %0, %1;" : "=f"(lg) : "f"(x));
    float e = lg * p;
    float r; asm("ex2.approx.f32 %0, %1;" : "=f"(r) : "f"(e)); return r;
}
__device__ __forceinline__ u64 pk(float x, float y) {
    u64 r; asm("mov.b64 %0, {%1,%2};" : "=l"(r) : "f"(x), "f"(y)); return r;
}
__device__ __forceinline__ void upk(u64 v, float& x, float& y) {
    asm("mov.b64 {%0,%1}, %2;" : "=f"(x), "=f"(y) : "l"(v));
}
__device__ __forceinline__ u64 fma2(u64 a, u64 b, u64 c) {
    u64 d; asm("fma.rn.f32x2 %0, %1, %2, %3;" : "=l"(d) : "l"(a), "l"(b), "l"(c)); return d;
}
__device__ __forceinline__ u64 mul2(u64 a, u64 b) {
    u64 d; asm("mul.rn.f32x2 %0, %1, %2;" : "=l"(d) : "l"(a), "l"(b)); return d;
}
__device__ __forceinline__ u64 rcp2(u64 v) {      // 2x MUFU
    float x, y; upk(v, x, y);
    return pk(frcp(x), frcp(y));
}
__device__ __forceinline__ float wredux(float v) {
    #pragma unroll
    for (int o = 16; o; o >>= 1) v += __shfl_xor_sync(0xffffffffu, v, o);
    return v;
}

// packed rcp seed; no cross-field borrow: low field >= bits(nr) for nr in [-3,-1]
#define MAGIC2 0xFEF311C3FEF311C3ULL

// Update pass: Z = sum (1+u*s)^-5.
// NSTEP=0: seed-only reciprocal (err ~5%; only feeds Aitken's s1 -> harmless).
// NSTEP=2: 2x Newton (err ~1e-5).
// Pairs 0..13 are mask-free; pairs 14,15 may hold +inf -> MUFU rcp (inf->0).
template<int NSTEP>
__device__ __forceinline__ float zpass_update(const u64* u2, float s)
{
    const u64 ONE2  = pk(1.0f, 1.0f);
    const u64 nONE2 = pk(-1.0f, -1.0f);
    const u64 TWO2  = pk(2.0f, 2.0f);
    const u64 sv    = pk(s, s);
    const u64 nsv   = pk(-s, -s);
    u64 z2 = pk(0.0f, 0.0f);
    #pragma unroll
    for (int i = 0; i < 14; ++i) {
        u64 nr2 = fma2(u2[i], nsv, nONE2);     // -(1+u*s) in [-3,-1]
        u64 y   = MAGIC2 - nr2;                // ~5% seed (ALU pipe)
        #pragma unroll
        for (int n = 0; n < NSTEP; ++n)
            y = mul2(y, fma2(nr2, y, TWO2));   // Newton
        u64 q2 = mul2(y, y);
        u64 q4 = mul2(q2, q2);
        z2 = fma2(q4, y, z2);                  // += r^-5
    }
    #pragma unroll
    for (int i = 14; i < 16; ++i) {
        u64 r2   = fma2(u2[i], sv, ONE2);      // inf for masked
        u64 inv2 = rcp2(r2);                   // 0 for masked
        u64 q2 = mul2(inv2, inv2);
        u64 q4 = mul2(q2, q2);
        z2 = fma2(q4, inv2, z2);
    }
    float zx, zy; upk(z2, zx, zy);
    return wredux(zx + zy);
}

// ---------------------------------------------------------------------------
// One warp per row; 32 elems/lane as 16 packed f32x2 regs.
// s1 from seed-only pass; s2 = g(s1), s3 = g(s2) (precise map); pass 3 also
// accumulates S1=Σw·inv, S6=Σw·inv⁶, S7=Σw·inv⁷ at inv = 1/(1+u*s2).
// Aitken sf from (s1,s2,s3)  [valid: s2,s3 are consecutive precise-g iterates;
// e1 may be arbitrary].  c = sf/s2 - 1 (~1e-3):
//   Σw/(u+zp)   ≈ sf ·S1                       (drop O(c) on tiny B_off term)
//   Σw/(u+zp)^6 ≈ sf⁶·(S6 - 6c(S6-S7))         (+O(c²)=2e-5)
// Block partial -> single packed-u64 atomicAdd; last arriver (counter in the
// high bits of the SAME atomic) decodes the returned total, computes wsum,
// writes out.  No fences, bitwise deterministic (integer adds commute).
// ---------------------------------------------------------------------------
__global__ __launch_bounds__(256)
void bitempered_row_kernel(const float* __restrict__ logits,
                           const int*   __restrict__ truth,
                           const float* __restrict__ weight,
                           float* __restrict__ out,
                           float A_off, float B_off, float dA, float dB)
{
    __shared__ float sm[8];
    __shared__ u64   sm_total;
    __shared__ int   sm_last;
    const int lane = threadIdx.x & 31;
    const int wib  = threadIdx.x >> 5;
    const int row  = blockIdx.x * 8 + wib;

    const int   t  = truth[row];                       // uniform per warp
    const float xt = logits[(size_t)row * C_CLS + t];  // truth-class logit
    const float wt = __ldg(weight + t);

    const float4* xrow = (const float4*)(logits + (size_t)row * C_CLS);

    u64 u2[16];
    float xmax = -INFINITY;
    #pragma unroll
    for (int j = 0; j < 8; ++j) {
        const int q = lane + 32 * j;            // float4 index, valid iff q < 250
        float4 v;
        if (q < 250) v = xrow[q];
        else         v = make_float4(-INFINITY, -INFINITY, -INFINITY, -INFINITY);
        u2[2*j]   = pk(v.x, v.y);
        u2[2*j+1] = pk(v.z, v.w);
        xmax = fmaxf(xmax, fmaxf(fmaxf(v.x, v.y), fmaxf(v.z, v.w)));
    }
    #pragma unroll
    for (int o = 16; o; o >>= 1)
        xmax = fmaxf(xmax, __shfl_xor_sync(0xffffffffu, xmax, o));

    {
        const u64 cm = pk(-0.2f, -0.2f);
        const u64 ca = pk(0.2f * xmax, 0.2f * xmax);
        #pragma unroll
        for (int i = 0; i < 16; ++i)
            u2[i] = fma2(u2[i], cm, ca);        // masked raw -inf -> +inf
    }

    // s1 (seed-only), s2 (precise)
    const float s1 = fpow_fast(zpass_update<0>(u2, 1.0f), -0.2f);
    const float s2 = fpow_fast(zpass_update<2>(u2, s1),  -0.2f);

    // Pass 3: precise map at s2 + weighted power sums S1,S6,S7
    const u64 ONE2  = pk(1.0f, 1.0f);
    const u64 nONE2 = pk(-1.0f, -1.0f);
    const u64 TWO2  = pk(2.0f, 2.0f);
    const u64 sv    = pk(s2, s2);
    const u64 nsv   = pk(-s2, -s2);
    const float4* w4 = (const float4*)weight;

    u64 z2 = pk(0.0f, 0.0f);
    u64 S1a = z2, S6a = z2, S7a = z2;
    #pragma unroll
    for (int j = 0; j < 8; ++j) {
        const int q = lane + 32 * j;
        float4 wv;
        if (q < 250) wv = w4[q];
        else         wv = make_float4(0.0f, 0.0f, 0.0f, 0.0f);
        u64 w2[2] = { pk(wv.x, wv.y), pk(wv.z, wv.w) };
        #pragma unroll
        for (int h = 0; h < 2; ++h) {
            const int i = 2*j + h;
            u64 y;
            if (i < 14) {                       // mask-free: FMA-pipe Newton
                u64 nr2 = fma2(u2[i], nsv, nONE2);
                y = MAGIC2 - nr2;
                y = mul2(y, fma2(nr2, y, TWO2));
                y = mul2(y, fma2(nr2, y, TWO2));
            } else {                            // MUFU (inf-safe: inv -> 0)
                u64 r2 = fma2(u2[i], sv, ONE2);
                y = rcp2(r2);
            }
            u64 q2 = mul2(y, y);
            u64 q4 = mul2(q2, q2);
            z2  = fma2(q4, y, z2);              // Z  += inv^5
            S1a = fma2(y,  w2[h], S1a);         // += w*inv
            u64 p6 = mul2(q4, q2);
            S6a = fma2(p6, w2[h], S6a);         // += w*inv^6
            u64 p7 = mul2(p6, y);
            S7a = fma2(p7, w2[h], S7a);         // += w*inv^7
        }
    }
    float a, b;
    upk(z2,  a, b); const float z3 = wredux(a + b);
    upk(S1a, a, b); const float S1 = wredux(a + b);
    upk(S6a, a, b); const float S6 = wredux(a + b);
    upk(S7a, a, b); const float S7 = wredux(a + b);

    if (lane == 0) {
        const float s3 = fpow_fast(z3, -0.2f);
        // Aitken extrapolation to the fixed point
        const float d1  = s2 - s1;
        const float d2  = s3 - s2;
        const float den = d2 - d1;
        float sf = s3;
        if (fabsf(den) > 1e-12f) sf = s3 - d2 * d2 * frcp(den);
        const float zp = frcp(sf);                    // u + zp = 1 - 0.2*(x-nc)
        const float c  = fmaf(sf, frcp(s2), -1.0f);   // sums taken at s2
        const float sf2 = sf * sf;
        const float sf6 = sf2 * sf2 * sf2;
        const float sumInv  = sf * S1;
        const float sumInv6 = sf6 * fmaf(-6.0f * c, S6 - S7, S6);
        const float ut   = fmaf(xt, -0.2f, 0.2f * xmax);
        const float invt = frcp(ut + zp);
        float acc = fmaf(-B_off, sumInv, sumInv6 * (1.0f / 1.2f));
        acc += wt * fmaf(-dB, invt, dA);
        sm[wib] = acc;
    }
    __syncthreads();

    if (threadIdx.x == 0) {
        float bs = 0.0f;
        #pragma unroll
        for (int i = 0; i < 8; ++i) bs += sm[i];
        long long llv = __float2ll_rn(bs * SCALE_F);        // |llv| << 2^39
        u64 contrib = (1ull << 52) + (u64)(llv + BIAS_LL);
        u64 old = atomicAdd(&g_acc, contrib);
        int last = ((old >> 52) == (u64)(NBLK - 1));
        sm_last = last;
        if (last) sm_total = old + contrib;   // counter bits wrapped to 0 exactly
    }
    __syncthreads();

    // last-arriving block finishes the reduction (no fence needed: the atomic
    // return value already contains every block's contribution)
    if (sm_last && wib == 0) {
        float ws = 0.0f;
        #pragma unroll
        for (int j = 0; j < 8; ++j) {
            const int q = lane + 32 * j;
            if (q < 250) {
                float4 wv = w4[q];
                ws += (wv.x + wv.y) + (wv.z + wv.w);
            }
        }
        ws = wredux(ws);
        if (lane == 0) {
            long long net = (long long)sm_total - ((long long)NBLK * BIAS_LL);
            const float lsum = (float)net * INV_SCALE;
            out[0] = lsum * ((float)C_CLS / ws) * (1.0f / (float)B_ROWS)
                   + A_off * (float)C_CLS;
            atomicExch(&g_acc, 0ull);          // reset for next graph replay
        }
    }
}

// ---------------------------------------------------------------------------
extern "C" void kernel_launch(void* const* d_in, const int* in_sizes, int n_in,
                              void* d_out, int out_size)
{
    const float* logits = (const float*)d_in[0];
    const int*   truth  = (const int*)  d_in[1];
    const float* weight = (const float*)d_in[2];
    float* out = (float*)d_out;

    const double T1 = 0.8, SM = 0.05;
    const double Cd = (double)C_CLS;
    const double y_on  = (1.0 - SM * Cd / (Cd - 1.0)) + SM / (Cd - 1.0);
    const double y_off = SM / (Cd - 1.0);
    auto logt1 = [](double v) { return (pow(v, 0.2) - 1.0) / 0.2; };
    auto Cy = [&](double y) {
        return y * logt1(y + 1e-10) - pow(y, 2.0 - T1) / (2.0 - T1);
    };
    const float A_on  = (float)(Cy(y_on)  + 5.0 * y_on);
    const float A_off = (float)(Cy(y_off) + 5.0 * y_off);
    const float B_on  = (float)(5.0 * y_on);
    const float B_off = (float)(5.0 * y_off);

    bitempered_row_kernel<<<NBLK, 256>>>(logits, truth, weight, out,
                                         A_off, B_off,
                                         A_on - A_off, B_on - B_off);
}

// round 10
// speedup vs baseline: 2.4204x; 1.1096x over previous
#include <cuda_runtime.h>
#include <math.h>

#define B_ROWS 32768
#define C_CLS  1000
#define NBLK   (B_ROWS / 8)

// packed accumulator: bits[63:52] arrival count, bits[51:0] biased fixed-point sum
__device__ unsigned long long g_acc;   // zero-init; self-resets each launch

typedef unsigned long long u64;

#define SCALE_F   268435456.0f           /* 2^28 */
#define INV_SCALE (1.0f / 268435456.0f)
#define BIAS_LL   (1ll << 39)
#define SUB_SCALE 3.90625f               /* 1000/256: subsample -> full Z */

__device__ __forceinline__ float frcp(float x) {
    float r; asm("rcp.approx.f32 %0, %1;" : "=f"(r) : "f"(x)); return r;
}
__device__ __forceinline__ float fpow_fast(float x, float p) {
    float lg; asm("lg2.approx.f32 %0, %1;" : "=f"(lg) : "f"(x));
    float e = lg * p;
    float r; asm("ex2.approx.f32 %0, %1;" : "=f"(r) : "f"(e)); return r;
}
__device__ __forceinline__ u64 pk(float x, float y) {
    u64 r; asm("mov.b64 %0, {%1,%2};" : "=l"(r) : "f"(x), "f"(y)); return r;
}
__device__ __forceinline__ void upk(u64 v, float& x, float& y) {
    asm("mov.b64 {%0,%1}, %2;" : "=f"(x), "=f"(y) : "l"(v));
}
__device__ __forceinline__ u64 fma2(u64 a, u64 b, u64 c) {
    u64 d; asm("fma.rn.f32x2 %0, %1, %2, %3;" : "=l"(d) : "l"(a), "l"(b), "l"(c)); return d;
}
__device__ __forceinline__ u64 mul2(u64 a, u64 b) {
    u64 d; asm("mul.rn.f32x2 %0, %1, %2;" : "=l"(d) : "l"(a), "l"(b)); return d;
}
__device__ __forceinline__ u64 add2(u64 a, u64 b) {
    u64 d; asm("add.rn.f32x2 %0, %1, %2;" : "=l"(d) : "l"(a), "l"(b)); return d;
}
__device__ __forceinline__ u64 rcp2(u64 v) {      // 2x MUFU
    float x, y; upk(v, x, y);
    return pk(frcp(x), frcp(y));
}
__device__ __forceinline__ float wredux(float v) {
    #pragma unroll
    for (int o = 16; o; o >>= 1) v += __shfl_xor_sync(0xffffffffu, v, o);
    return v;
}

// packed rcp seed; no cross-field borrow: low field >= bits(nr) for nr in [-3,-1]
#define MAGIC2 0xFEF311C3FEF311C3ULL

// Subsampled Z pass over pairs 0..NPAIR-1 (all mask-free; elements 0..8*NPAIR-1
// per lane-stride): Z_sub = sum (1+u*s)^-5.  NSTEP Newton refinements.
template<int NPAIR, int NSTEP>
__device__ __forceinline__ float zpass_sub(const u64* u2, float s)
{
    const u64 nONE2 = pk(-1.0f, -1.0f);
    const u64 TWO2  = pk(2.0f, 2.0f);
    const u64 nsv   = pk(-s, -s);
    u64 z2 = pk(0.0f, 0.0f);
    #pragma unroll
    for (int i = 0; i < NPAIR; ++i) {
        u64 nr2 = fma2(u2[i], nsv, nONE2);     // -(1+u*s) in [-3,-1]
        u64 y   = MAGIC2 - nr2;                // ~5% seed (ALU pipe)
        #pragma unroll
        for (int n = 0; n < NSTEP; ++n)
            y = mul2(y, fma2(nr2, y, TWO2));   // Newton
        u64 q2 = mul2(y, y);
        u64 q4 = mul2(q2, q2);
        z2 = fma2(q4, y, z2);                  // += r^-5
    }
    float zx, zy; upk(z2, zx, zy);
    return wredux(zx + zy);
}

// ---------------------------------------------------------------------------
// One warp per row; 32 elems/lane as 16 packed f32x2 regs.
// Bootstrap s on a 256-element subsample (pairs 0..3):
//   s1 = g~sub(1)  (seed-only),  s_pred = g~sub(s1)  (1-Newton).
// Full pass at s_pred (2-Newton) accumulates  Z5=Σinv⁵, Z6=Σinv⁶ (unweighted)
// and S1=Σw·inv, S2=Σw·inv², S6=Σw·inv⁶, S7=Σw·inv⁷.
// Newton fixed-point extrapolation (g' = g·(1-Z6/Z5)/s via Σu·inv⁶=(Z5-Z6)/s):
//   sf = s_pred + (g - s_pred)/(1 - g'),  err ~ e_pred² ≈ 1e-5
// c = sf/s_pred - 1 (~6e-3):
//   Σw/(u+zp)   ≈ sf ·(S1 - c(S1-S2))
//   Σw/(u+zp)^6 ≈ sf⁶·(S6 - 6c(S6-S7))
// Block partial -> fence-free packed-u64 atomicAdd finish (R9 scheme).
// ---------------------------------------------------------------------------
__global__ __launch_bounds__(256)
void bitempered_row_kernel(const float* __restrict__ logits,
                           const int*   __restrict__ truth,
                           const float* __restrict__ weight,
                           float* __restrict__ out,
                           float A_off, float B_off, float dA, float dB)
{
    __shared__ float sm[8];
    __shared__ u64   sm_total;
    __shared__ int   sm_last;
    const int lane = threadIdx.x & 31;
    const int wib  = threadIdx.x >> 5;
    const int row  = blockIdx.x * 8 + wib;

    const int   t  = truth[row];                       // uniform per warp
    const float xt = logits[(size_t)row * C_CLS + t];  // truth-class logit
    const float wt = __ldg(weight + t);

    const float4* xrow = (const float4*)(logits + (size_t)row * C_CLS);

    u64 u2[16];
    float xmax = -INFINITY;
    #pragma unroll
    for (int j = 0; j < 8; ++j) {
        const int q = lane + 32 * j;            // float4 index, valid iff q < 250
        float4 v;
        if (q < 250) v = xrow[q];
        else         v = make_float4(-INFINITY, -INFINITY, -INFINITY, -INFINITY);
        u2[2*j]   = pk(v.x, v.y);
        u2[2*j+1] = pk(v.z, v.w);
        xmax = fmaxf(xmax, fmaxf(fmaxf(v.x, v.y), fmaxf(v.z, v.w)));
    }
    #pragma unroll
    for (int o = 16; o; o >>= 1)
        xmax = fmaxf(xmax, __shfl_xor_sync(0xffffffffu, xmax, o));

    {
        const u64 cm = pk(-0.2f, -0.2f);
        const u64 ca = pk(0.2f * xmax, 0.2f * xmax);
        #pragma unroll
        for (int i = 0; i < 16; ++i)
            u2[i] = fma2(u2[i], cm, ca);        // masked raw -inf -> +inf
    }

    // Subsampled bootstrap (sampling err ~3% on Z -> ~0.6% on s)
    const float s1     = fpow_fast(zpass_sub<4,0>(u2, 1.0f) * SUB_SCALE, -0.2f);
    const float s_pred = fpow_fast(zpass_sub<4,1>(u2, s1)   * SUB_SCALE, -0.2f);

    // Full pass at s_pred: Z5, Z6 + weighted sums
    const u64 ONE2  = pk(1.0f, 1.0f);
    const u64 nONE2 = pk(-1.0f, -1.0f);
    const u64 TWO2  = pk(2.0f, 2.0f);
    const u64 sv    = pk(s_pred, s_pred);
    const u64 nsv   = pk(-s_pred, -s_pred);
    const float4* w4 = (const float4*)weight;

    u64 z5a = pk(0.0f, 0.0f);
    u64 z6a = z5a, S1a = z5a, S2a = z5a, S6a = z5a, S7a = z5a;
    #pragma unroll
    for (int j = 0; j < 8; ++j) {
        const int q = lane + 32 * j;
        float4 wv;
        if (q < 250) wv = w4[q];
        else         wv = make_float4(0.0f, 0.0f, 0.0f, 0.0f);
        u64 w2[2] = { pk(wv.x, wv.y), pk(wv.z, wv.w) };
        #pragma unroll
        for (int h = 0; h < 2; ++h) {
            const int i = 2*j + h;
            u64 y;
            if (i < 14) {                       // mask-free: FMA-pipe Newton
                u64 nr2 = fma2(u2[i], nsv, nONE2);
                y = MAGIC2 - nr2;
                y = mul2(y, fma2(nr2, y, TWO2));
                y = mul2(y, fma2(nr2, y, TWO2));
            } else {                            // MUFU (inf-safe: inv -> 0)
                u64 r2 = fma2(u2[i], sv, ONE2);
                y = rcp2(r2);
            }
            u64 q2 = mul2(y, y);
            u64 q4 = mul2(q2, q2);
            z5a = fma2(q4, y, z5a);             // Z5 += inv^5
            u64 p6 = mul2(q4, q2);
            z6a = add2(z6a, p6);                // Z6 += inv^6
            S1a = fma2(y,  w2[h], S1a);         // += w*inv
            S2a = fma2(q2, w2[h], S2a);         // += w*inv^2
            S6a = fma2(p6, w2[h], S6a);         // += w*inv^6
            u64 p7 = mul2(p6, y);
            S7a = fma2(p7, w2[h], S7a);         // += w*inv^7
        }
    }
    float a, b;
    upk(z5a, a, b); const float Z5 = wredux(a + b);
    upk(z6a, a, b); const float Z6 = wredux(a + b);
    upk(S1a, a, b); const float S1 = wredux(a + b);
    upk(S2a, a, b); const float S2 = wredux(a + b);
    upk(S6a, a, b); const float S6 = wredux(a + b);
    upk(S7a, a, b); const float S7 = wredux(a + b);

    if (lane == 0) {
        const float g   = fpow_fast(Z5, -0.2f);             // g(s_pred)
        const float gp  = g * (1.0f - Z6 * frcp(Z5)) * frcp(s_pred);  // g'(s_pred)
        const float sf  = s_pred + (g - s_pred) * frcp(1.0f - gp);    // Newton FP step
        const float zp  = frcp(sf);                   // u + zp = 1 - 0.2*(x-nc)
        const float c   = fmaf(sf, frcp(s_pred), -1.0f);
        const float sf2 = sf * sf;
        const float sf6 = sf2 * sf2 * sf2;
        const float sumInv  = sf  * fmaf(-c, S1 - S2, S1);
        const float sumInv6 = sf6 * fmaf(-6.0f * c, S6 - S7, S6);
        const float ut   = fmaf(xt, -0.2f, 0.2f * xmax);
        const float invt = frcp(ut + zp);
        float acc = fmaf(-B_off, sumInv, sumInv6 * (1.0f / 1.2f));
        acc += wt * fmaf(-dB, invt, dA);
        sm[wib] = acc;
    }
    __syncthreads();

    if (threadIdx.x == 0) {
        float bs = 0.0f;
        #pragma unroll
        for (int i = 0; i < 8; ++i) bs += sm[i];
        long long llv = __float2ll_rn(bs * SCALE_F);        // |llv| << 2^39
        u64 contrib = (1ull << 52) + (u64)(llv + BIAS_LL);
        u64 old = atomicAdd(&g_acc, contrib);
        int last = ((old >> 52) == (u64)(NBLK - 1));
        sm_last = last;
        if (last) sm_total = old + contrib;   // counter bits wrapped to 0 exactly
    }
    __syncthreads();

    // last-arriving block finishes (atomic return already holds the full sum)
    if (sm_last && wib == 0) {
        float ws = 0.0f;
        #pragma unroll
        for (int j = 0; j < 8; ++j) {
            const int q = lane + 32 * j;
            if (q < 250) {
                float4 wv = w4[q];
                ws += (wv.x + wv.y) + (wv.z + wv.w);
            }
        }
        ws = wredux(ws);
        if (lane == 0) {
            long long net = (long long)sm_total - ((long long)NBLK * BIAS_LL);
            const float lsum = (float)net * INV_SCALE;
            out[0] = lsum * ((float)C_CLS / ws) * (1.0f / (float)B_ROWS)
                   + A_off * (float)C_CLS;
            atomicExch(&g_acc, 0ull);          // reset for next graph replay
        }
    }
}

// ---------------------------------------------------------------------------
extern "C" void kernel_launch(void* const* d_in, const int* in_sizes, int n_in,
                              void* d_out, int out_size)
{
    const float* logits = (const float*)d_in[0];
    const int*   truth  = (const int*)  d_in[1];
    const float* weight = (const float*)d_in[2];
    float* out = (float*)d_out;

    const double T1 = 0.8, SM = 0.05;
    const double Cd = (double)C_CLS;
    const double y_on  = (1.0 - SM * Cd / (Cd - 1.0)) + SM / (Cd - 1.0);
    const double y_off = SM / (Cd - 1.0);
    auto logt1 = [](double v) { return (pow(v, 0.2) - 1.0) / 0.2; };
    auto Cy = [&](double y) {
        return y * logt1(y + 1e-10) - pow(y, 2.0 - T1) / (2.0 - T1);
    };
    const float A_on  = (float)(Cy(y_on)  + 5.0 * y_on);
    const float A_off = (float)(Cy(y_off) + 5.0 * y_off);
    const float B_on  = (float)(5.0 * y_on);
    const float B_off = (float)(5.0 * y_off);

    bitempered_row_kernel<<<NBLK, 256>>>(logits, truth, weight, out,
                                         A_off, B_off,
                                         A_on - A_off, B_on - B_off);
}